// round 7
// baseline (speedup 1.0000x reference)
#include <cuda_runtime.h>

// GVCNN group pooling collapsed to out[n,c] = sum_v coef[n,gid[n,v]] * RPs[n,v,c].
//
// One 128-thread block per sample, views split across 4 warps (warp w owns
// views 3w..3w+2; each lane holds float4 chunks {lane, lane+32} of its 3
// views -> 6 batched coalesced LDG.128 per thread, MLP preserved).
//
// vs R6 (2 warps x 6 views, 72 regs, 24 warps/SM, DRAM 68.8%): halving the
// per-warp tile cuts regs to ~55 -> 8 CTAs = 32 warps/SM (50% occ) and
// shortens each warp's serial tail (15 SHFLs vs 30), so load phases of more
// warps tile over compute tails -> higher DRAM duty cycle.
//
// Binning runs once, warp-parallel in warp 0 (match_any+popc histogram,
// shfl-gather numerator in increasing-view order). Final combine: each warp
// stores its 3-view partial to smem, threads 0..63 sum 4 partials + store.

#define NV 12
#define EPSF 1e-6f

__global__ __launch_bounds__(128, 8) void gvcnn_kernel(
    const float4* __restrict__ RPs4,   // [N, 12, 64] float4
    const float4* __restrict__ w4p,    // [64] float4
    const float*  __restrict__ b,
    float4*       __restrict__ out4)   // [N, 64] float4
{
    const int lane = threadIdx.x & 31;
    const int wid  = threadIdx.x >> 5;          // 0..3
    const size_t n = blockIdx.x;
    const int v0   = wid * 3;                   // first owned view

    __shared__ float  s_y[NV];
    __shared__ float  s_coef[NV];
    __shared__ float4 s_part[4][64];

    const float4* base = RPs4 + n * (NV * 64);
    const float4 wa = w4p[lane];
    const float4 wb = w4p[lane + 32];

    // ---- batched loads: 6 independent coalesced LDG.128, nothing between ----
    float4 r0[3], r1[3];
#pragma unroll
    for (int j = 0; j < 3; j++) {
        r0[j] = base[(v0 + j) * 64 + lane];
        r1[j] = base[(v0 + j) * 64 + 32 + lane];
    }

    // ---- 3 dot partials, reduced fully in-warp (chunks lane,lane+32 cover all 64) ----
    float p[3];
#pragma unroll
    for (int j = 0; j < 3; j++) {
        p[j] = r0[j].x * wa.x + r0[j].y * wa.y + r0[j].z * wa.z + r0[j].w * wa.w
             + r1[j].x * wb.x + r1[j].y * wb.y + r1[j].z * wb.z + r1[j].w * wb.w;
    }
#pragma unroll
    for (int off = 16; off > 0; off >>= 1) {
#pragma unroll
        for (int j = 0; j < 3; j++)
            p[j] += __shfl_xor_sync(0xffffffffu, p[j], off);
    }
    if (lane == 0) {
#pragma unroll
        for (int j = 0; j < 3; j++) s_y[v0 + j] = p[j];
    }
    __syncthreads();

    // ---- warp-parallel binning, ONCE per sample (warp 0; lane v owns view v) ----
    if (wid == 0) {
        const float bb = b[0];
        const float y  = s_y[lane < NV ? lane : 0];
        const float x  = fabsf(y + bb) + EPSF;
        const float s  = x / (1.0f + x);                 // == sigmoid(log(x))
        const int  gid = min((int)(s * 10.0f), 9) >> 1;  // 0..4

        // bin histogram in one instruction (only view lanes counted)
        const unsigned mask = __match_any_sync(0xffffffffu, gid) & 0xFFFu;
        const int      gszI = __popc(mask);              // >=1 for lane<12
        const float    gszF = (float)(gszI | (gszI == 0));
        const float    val  = ceilf(s * gszF);

        // numerator: sum of val over matching lanes, increasing-v order
        float numer = 0.f;
#pragma unroll
        for (int u = 0; u < NV; u++) {
            const float vu = __shfl_sync(0xffffffffu, val, u);
            if ((mask >> u) & 1u) numer += vu;
        }
        const float gs = numer / (gszF + EPSF);          // reference group_score

        // total = sum over bins of gs  ==  sum over views of gs/gsize
        float t = (lane < NV) ? gs / gszF : 0.f;
#pragma unroll
        for (int off = 16; off > 0; off >>= 1)
            t += __shfl_xor_sync(0xffffffffu, t, off);

        const float coef = gs / (gszF + EPSF) * (1.0f / (t + EPSF));
        if (lane < NV) s_coef[lane] = coef;
    }
    __syncthreads();

    // ---- per-warp weighted partial over its 3 views (from registers) ----
    float cf[3];
#pragma unroll
    for (int j = 0; j < 3; j++) cf[j] = s_coef[v0 + j];

    float4 a0 = make_float4(0.f, 0.f, 0.f, 0.f);
    float4 a1 = make_float4(0.f, 0.f, 0.f, 0.f);
#pragma unroll
    for (int j = 0; j < 3; j++) {
        a0.x += cf[j] * r0[j].x;  a0.y += cf[j] * r0[j].y;
        a0.z += cf[j] * r0[j].z;  a0.w += cf[j] * r0[j].w;
        a1.x += cf[j] * r1[j].x;  a1.y += cf[j] * r1[j].y;
        a1.z += cf[j] * r1[j].z;  a1.w += cf[j] * r1[j].w;
    }
    s_part[wid][lane]      = a0;
    s_part[wid][32 + lane] = a1;
    __syncthreads();

    // ---- threads 0..63 fold the 4 view-partials, coalesced store ----
    if (threadIdx.x < 64) {
        const int u = threadIdx.x;
        float4 acc = s_part[0][u];
        const float4 t1 = s_part[1][u];
        const float4 t2 = s_part[2][u];
        const float4 t3 = s_part[3][u];
        acc.x += t1.x + t2.x + t3.x;
        acc.y += t1.y + t2.y + t3.y;
        acc.z += t1.z + t2.z + t3.z;
        acc.w += t1.w + t2.w + t3.w;
        out4[n * 64 + u] = acc;
    }
}

extern "C" void kernel_launch(void* const* d_in, const int* in_sizes, int n_in,
                              void* d_out, int out_size)
{
    const float4* RPs4 = (const float4*)d_in[0];   // [8192,12,256] f32
    const float4* w4p  = (const float4*)d_in[1];   // [256] f32
    const float*  b    = (const float*)d_in[2];    // [1] f32
    float4* out4       = (float4*)d_out;           // [8192,256] f32

    const int n = in_sizes[0] / (NV * 256);        // 8192
    gvcnn_kernel<<<n, 128>>>(RPs4, w4p, b, out4);
}

// round 8
// speedup vs baseline: 1.0746x; 1.0746x over previous
#include <cuda_runtime.h>

// GVCNN group pooling collapsed to out[n,c] = sum_v coef[n,gid[n,v]] * RPs[n,v,c].
//
// R6 skeleton (64-thread block = 2 warps; warp h owns views 6h..6h+5; lane
// holds float4 chunks {lane, lane+32}; warp-parallel binning in warp 0), but
// each block now processes 4 samples with a DOUBLE-BUFFERED register tile:
// the next sample's 12 batched LDG.128s are in flight while the current
// sample's reduce/binning/epilogue tail runs. R6/R7 showed a ~0.6 DRAM duty
// cycle from that uncovered tail; pipelining covers it.

#define NV 12
#define SPB 4            // samples per block
#define EPSF 1e-6f

__global__ __launch_bounds__(64, 8) void gvcnn_kernel(
    const float4* __restrict__ RPs4,   // [N, 12, 64] float4
    const float4* __restrict__ w4p,    // [64] float4
    const float*  __restrict__ b,
    float4*       __restrict__ out4)   // [N, 64] float4
{
    const int lane = threadIdx.x & 31;
    const int half = threadIdx.x >> 5;          // warp 0 or 1
    const int v0   = half * 6;                  // first owned view
    const size_t n0 = (size_t)blockIdx.x * SPB;

    __shared__ float  s_y[NV];
    __shared__ float  s_coef[NV];
    __shared__ float4 s_acc[64];

    const float4 wa = w4p[lane];
    const float4 wb = w4p[lane + 32];
    const float  bb = b[0];

    // ---- batched tile load: 12 independent coalesced LDG.128 ----
    auto load_tile = [&](float4 (&r0)[6], float4 (&r1)[6], size_t n) {
        const float4* base = RPs4 + n * (NV * 64) + lane;
#pragma unroll
        for (int j = 0; j < 6; j++) {
            r0[j] = base[(v0 + j) * 64];
            r1[j] = base[(v0 + j) * 64 + 32];
        }
    };

    // ---- full per-sample compute: reduce -> binning -> epilogue -> store ----
    auto process = [&](const float4 (&r0)[6], const float4 (&r1)[6], size_t n) {
        float p[6];
#pragma unroll
        for (int j = 0; j < 6; j++) {
            p[j] = r0[j].x * wa.x + r0[j].y * wa.y + r0[j].z * wa.z + r0[j].w * wa.w
                 + r1[j].x * wb.x + r1[j].y * wb.y + r1[j].z * wb.z + r1[j].w * wb.w;
        }
#pragma unroll
        for (int off = 16; off > 0; off >>= 1) {
#pragma unroll
            for (int j = 0; j < 6; j++)
                p[j] += __shfl_xor_sync(0xffffffffu, p[j], off);
        }
        if (lane == 0) {
#pragma unroll
            for (int j = 0; j < 6; j++) s_y[v0 + j] = p[j];
        }
        __syncthreads();

        // warp-parallel binning, once per sample (warp 0; lane v owns view v)
        if (half == 0) {
            const float y  = s_y[lane < NV ? lane : 0];
            const float x  = fabsf(y + bb) + EPSF;
            const float s  = x / (1.0f + x);                 // == sigmoid(log(x))
            const int  gid = min((int)(s * 10.0f), 9) >> 1;  // 0..4

            const unsigned mask = __match_any_sync(0xffffffffu, gid) & 0xFFFu;
            const int      gszI = __popc(mask);
            const float    gszF = (float)(gszI | (gszI == 0));
            const float    val  = ceilf(s * gszF);

            float numer = 0.f;
#pragma unroll
            for (int u = 0; u < NV; u++) {
                const float vu = __shfl_sync(0xffffffffu, val, u);
                if ((mask >> u) & 1u) numer += vu;
            }
            const float gs = numer / (gszF + EPSF);          // group_score

            float t = (lane < NV) ? gs / gszF : 0.f;
#pragma unroll
            for (int off = 16; off > 0; off >>= 1)
                t += __shfl_xor_sync(0xffffffffu, t, off);

            const float coef = gs / (gszF + EPSF) * (1.0f / (t + EPSF));
            if (lane < NV) s_coef[lane] = coef;
        }
        __syncthreads();

        float cf[6];
#pragma unroll
        for (int j = 0; j < 6; j++) cf[j] = s_coef[v0 + j];

        float4 a0 = make_float4(0.f, 0.f, 0.f, 0.f);
        float4 a1 = make_float4(0.f, 0.f, 0.f, 0.f);
#pragma unroll
        for (int j = 0; j < 6; j++) {
            a0.x += cf[j] * r0[j].x;  a0.y += cf[j] * r0[j].y;
            a0.z += cf[j] * r0[j].z;  a0.w += cf[j] * r0[j].w;
            a1.x += cf[j] * r1[j].x;  a1.y += cf[j] * r1[j].y;
            a1.z += cf[j] * r1[j].z;  a1.w += cf[j] * r1[j].w;
        }

        if (half == 1) {
            s_acc[lane]      = a0;
            s_acc[32 + lane] = a1;
        }
        __syncthreads();
        if (half == 0) {
            const float4 t0 = s_acc[lane];
            const float4 t1 = s_acc[32 + lane];
            a0.x += t0.x;  a0.y += t0.y;  a0.z += t0.z;  a0.w += t0.w;
            a1.x += t1.x;  a1.y += t1.y;  a1.z += t1.z;  a1.w += t1.w;
            out4[n * 64 + lane]      = a0;
            out4[n * 64 + 32 + lane] = a1;
        }
    };

    // ---- software pipeline: next tile's loads in flight during compute ----
    float4 A0[6], A1[6], B0[6], B1[6];
    load_tile(A0, A1, n0);
    load_tile(B0, B1, n0 + 1);
    process(A0, A1, n0);
    load_tile(A0, A1, n0 + 2);
    process(B0, B1, n0 + 1);
    load_tile(B0, B1, n0 + 3);
    process(A0, A1, n0 + 2);
    process(B0, B1, n0 + 3);
}

extern "C" void kernel_launch(void* const* d_in, const int* in_sizes, int n_in,
                              void* d_out, int out_size)
{
    const float4* RPs4 = (const float4*)d_in[0];   // [8192,12,256] f32
    const float4* w4p  = (const float4*)d_in[1];   // [256] f32
    const float*  b    = (const float*)d_in[2];    // [1] f32
    float4* out4       = (float4*)d_out;           // [8192,256] f32

    const int n = in_sizes[0] / (NV * 256);        // 8192
    gvcnn_kernel<<<n / SPB, 64>>>(RPs4, w4p, b, out4);
}